// round 10
// baseline (speedup 1.0000x reference)
#include <cuda_runtime.h>
#include <cuda_fp16.h>
#include <cstdint>

#define E_TOT    131072
#define DDIM     128
#define KTOT     2048
#define TILE_E   64
#define NTHREADS 256
#define NCHUNKS  64
#define U2STRIDE 66            // half2 units per row (64 + 2 pad -> conflict-free)

// ---- SMEM byte offsets ----
#define U_OFF    0             // 64 * 66 * 4 = 16896
#define V_OFF    16896
#define S3_OFF   33792         // 128 f
#define Q3_OFF   34304
#define CA_OFF   34816         // 16 f
#define CB_OFF   34880
#define CD_OFF   34944
#define ROW_OFF  35008         // 64 i
#define COL_OFF  35264
#define TYP_OFF  35520
#define DS_OFF   35776         // 4 * 64 f = 1024
#define SMEM_BYTES 36864

// fc_w in fp16, fragment-major: [chunk][s][nblk][lane] * 4 halves (8B units)
// lane = gid*4+tig; halves = {B[c=2tig][n], B[2tig+1][n], B[8+2tig][n], B[9+2tig][n]}
// n = nblk*8+gid; j = chunk*2+s; klog = c*128+j
__device__ __half g_Bh[NCHUNKS * 2 * 16 * 32 * 4];

__device__ __forceinline__ void mma_f16(float* c, uint32_t a0, uint32_t a1,
                                        uint32_t a2, uint32_t a3,
                                        uint32_t b0, uint32_t b1) {
    asm volatile(
        "mma.sync.aligned.m16n8k16.row.col.f32.f16.f16.f32 "
        "{%0,%1,%2,%3}, {%4,%5,%6,%7}, {%8,%9}, {%0,%1,%2,%3};"
        : "+f"(c[0]), "+f"(c[1]), "+f"(c[2]), "+f"(c[3])
        : "r"(a0), "r"(a1), "r"(a2), "r"(a3), "r"(b0), "r"(b1));
}
__device__ __forceinline__ uint32_t h2u(__half2 x) { return *(uint32_t*)&x; }

// ===== prep: fragment-major fp16 B from fc_w (identical to R8/R9, proven) =====
extern "C" __global__ void conve_prep(const float* __restrict__ fc_w)
{
    const int idx = blockIdx.x * 256 + threadIdx.x;     // 0..65535 (8B units)
    const int lane  = idx & 31;
    const int nblk  = (idx >> 5) & 15;
    const int s     = (idx >> 9) & 1;
    const int chunk = idx >> 10;
    const int gid = lane >> 2;
    const int tig = lane & 3;
    const int n = nblk * 8 + gid;
    const int j = chunk * 2 + s;

    const int c0 = 2 * tig, c1 = 2 * tig + 1, c2 = 8 + 2 * tig, c3 = 9 + 2 * tig;
    float f0 = fc_w[(long)(c0 * 128 + j) * DDIM + n];
    float f1 = fc_w[(long)(c1 * 128 + j) * DDIM + n];
    float f2 = fc_w[(long)(c2 * 128 + j) * DDIM + n];
    float f3 = fc_w[(long)(c3 * 128 + j) * DDIM + n];
    __half2* dst = (__half2*)(g_Bh + (long)idx * 4);
    dst[0] = __floats2half2_rn(f0, f1);
    dst[1] = __floats2half2_rn(f2, f3);
}

// ===== main: 3 CTAs/SM, 8 uniform warps, zero hot-loop sync =====
extern "C" __global__ void __launch_bounds__(NTHREADS, 3)
conve_main(const float* __restrict__ h, const float* __restrict__ g,
           const int* __restrict__ eidx, const int* __restrict__ etype,
           const float* __restrict__ conv_w, const float* __restrict__ conv_b,
           const float* __restrict__ fc_b,
           const float* __restrict__ bn1g, const float* __restrict__ bn1b,
           const float* __restrict__ bn1m, const float* __restrict__ bn1v,
           const float* __restrict__ bn3g, const float* __restrict__ bn3b,
           const float* __restrict__ bn3m, const float* __restrict__ bn3v,
           float* __restrict__ out)
{
    extern __shared__ char smc[];
    __half2* U2 = (__half2*)(smc + U_OFF);
    __half2* V2 = (__half2*)(smc + V_OFF);
    float* S3 = (float*)(smc + S3_OFF);
    float* Q3 = (float*)(smc + Q3_OFF);
    float* CA = (float*)(smc + CA_OFF);
    float* CB = (float*)(smc + CB_OFF);
    float* CD = (float*)(smc + CD_OFF);
    int* ROW = (int*)(smc + ROW_OFF);
    int* COL = (int*)(smc + COL_OFF);
    int* TYP = (int*)(smc + TYP_OFF);

    const int tid  = threadIdx.x;
    const int wid  = tid >> 5;
    const int lane = tid & 31;
    const int gid  = lane >> 2;
    const int tig  = lane & 3;
    const int e0   = blockIdx.x * TILE_E;

    if (tid < DDIM) {
        float s = bn3g[tid] * rsqrtf(bn3v[tid] + 1e-5f);
        S3[tid] = s;
        Q3[tid] = fc_b[tid] * s + bn3b[tid] - bn3m[tid] * s;
    }
    if (tid < TILE_E) {
        ROW[tid] = eidx[e0 + tid];
        COL[tid] = eidx[E_TOT + e0 + tid];
        TYP[tid] = etype[e0 + tid];
    }
    if (tid < 16) {
        float s1 = bn1g[0] * rsqrtf(bn1v[0] + 1e-5f);
        float b1 = bn1b[0] - bn1m[0] * s1;
        float w0 = conv_w[tid * 2], w1 = conv_w[tid * 2 + 1];
        CA[tid] = w0 * s1;
        CB[tid] = w1 * s1;
        CD[tid] = (w0 + w1) * b1 + conv_b[tid];
    }
    __syncthreads();

    // ---- gather h[row], g[type] -> fp16 SMEM [row][j-pair], once ----
    {
        const int row = tid >> 2;
        const int jq  = tid & 3;            // 32 j-values each
        const float* hp = h + (long)ROW[row] * DDIM + jq * 32;
        const float* gp = g + (long)TYP[row] * DDIM + jq * 32;
#pragma unroll
        for (int i = 0; i < 8; i++) {
            const float4 fu = __ldg((const float4*)(hp + i * 4));
            const float4 fv = __ldg((const float4*)(gp + i * 4));
            __half2 u0 = __floats2half2_rn(fu.x, fu.y);
            __half2 u1 = __floats2half2_rn(fu.z, fu.w);
            __half2 v0 = __floats2half2_rn(fv.x, fv.y);
            __half2 v1 = __floats2half2_rn(fv.z, fv.w);
            const int o = row * U2STRIDE + jq * 16 + i * 2;
            U2[o] = u0; U2[o + 1] = u1;
            V2[o] = v0; V2[o + 1] = v1;
        }
    }
    __syncthreads();

    // ---- per-lane channel-pair coefficients (half2) ----
    __half2 ca2[2], cb2[2], cd2[2];
#pragma unroll
    for (int p = 0; p < 2; p++) {
        const int c = p * 8 + 2 * tig;
        ca2[p] = __floats2half2_rn(CA[c], CA[c + 1]);
        cb2[p] = __floats2half2_rn(CB[c], CB[c + 1]);
        cd2[p] = __floats2half2_rn(CD[c], CD[c + 1]);
    }
    const __half2 zero2 = __floats2half2_rn(0.0f, 0.0f);

    const int ebase = (wid & 1) * 32;
    const int nblk0 = (wid >> 1) * 4;
    const int r0    = ebase + gid;

    float acc[2][4][4];
#pragma unroll
    for (int mt = 0; mt < 2; mt++)
#pragma unroll
        for (int nt = 0; nt < 4; nt++)
#pragma unroll
            for (int q = 0; q < 4; q++) acc[mt][nt][q] = 0.0f;

    // ---- B fragments: s-step ping-pong (prefetch distance = 2 s-steps) ----
    const uint2* Bbase = (const uint2*)g_Bh + nblk0 * 32 + lane;
    uint2 P0[4], P1[4];
#pragma unroll
    for (int nt = 0; nt < 4; nt++) P0[nt] = __ldg(Bbase + nt * 32);          // t=0
#pragma unroll
    for (int nt = 0; nt < 4; nt++) P1[nt] = __ldg(Bbase + 512 + nt * 32);    // t=1

    for (int chunk = 0; chunk < NCHUNKS; chunk++) {
        // u/v half2 (j0, j0+1) for this lane's 4 rows
        __half2 u2[4], v2[4];
#pragma unroll
        for (int q = 0; q < 4; q++) {
            const int o = (r0 + q * 8) * U2STRIDE + chunk;
            u2[q] = U2[o];
            v2[q] = V2[o];
        }
        const int t0 = 2 * chunk;

        // ---- s = 0 ----
        {
            uint32_t flo[4], fhi[4];
#pragma unroll
            for (int q = 0; q < 4; q++) {
                const __half2 uu = __low2half2(u2[q]);
                const __half2 vv = __low2half2(v2[q]);
                __half2 t0h = __hfma2(cb2[0], vv, cd2[0]);
                __half2 t1h = __hfma2(cb2[1], vv, cd2[1]);
                t0h = __hmax2(__hfma2(ca2[0], uu, t0h), zero2);
                t1h = __hmax2(__hfma2(ca2[1], uu, t1h), zero2);
                flo[q] = h2u(t0h);
                fhi[q] = h2u(t1h);
            }
#pragma unroll
            for (int nt = 0; nt < 4; nt++)
#pragma unroll
                for (int mt = 0; mt < 2; mt++)
                    mma_f16(acc[mt][nt],
                            flo[2 * mt], flo[2 * mt + 1],
                            fhi[2 * mt], fhi[2 * mt + 1],
                            P0[nt].x, P0[nt].y);
            if (t0 + 2 < 2 * NCHUNKS) {
                const uint2* bn = Bbase + (t0 + 2) * 512;
#pragma unroll
                for (int nt = 0; nt < 4; nt++) P0[nt] = __ldg(bn + nt * 32);
            }
        }
        // ---- s = 1 ----
        {
            uint32_t flo[4], fhi[4];
#pragma unroll
            for (int q = 0; q < 4; q++) {
                const __half2 uu = __high2half2(u2[q]);
                const __half2 vv = __high2half2(v2[q]);
                __half2 t0h = __hfma2(cb2[0], vv, cd2[0]);
                __half2 t1h = __hfma2(cb2[1], vv, cd2[1]);
                t0h = __hmax2(__hfma2(ca2[0], uu, t0h), zero2);
                t1h = __hmax2(__hfma2(ca2[1], uu, t1h), zero2);
                flo[q] = h2u(t0h);
                fhi[q] = h2u(t1h);
            }
#pragma unroll
            for (int nt = 0; nt < 4; nt++)
#pragma unroll
                for (int mt = 0; mt < 2; mt++)
                    mma_f16(acc[mt][nt],
                            flo[2 * mt], flo[2 * mt + 1],
                            fhi[2 * mt], fhi[2 * mt + 1],
                            P1[nt].x, P1[nt].y);
            if (t0 + 3 < 2 * NCHUNKS) {
                const uint2* bn = Bbase + (t0 + 3) * 512;
#pragma unroll
                for (int nt = 0; nt < 4; nt++) P1[nt] = __ldg(bn + nt * 32);
            }
        }
    }

    // ---- epilogue: bn3 + relu + dot(h[col]) ----
    long cbase[4];
#pragma unroll
    for (int rr = 0; rr < 4; rr++) {
        const int e = ebase + (rr >> 1) * 16 + (rr & 1) * 8 + gid;
        cbase[rr] = (long)COL[e] * DDIM;
    }
    float dotp[4] = {0.f, 0.f, 0.f, 0.f};
#pragma unroll
    for (int nt = 0; nt < 4; nt++) {
        const int n = (wid >> 1) * 32 + nt * 8 + 2 * tig;
        const float2 s3 = *(const float2*)&S3[n];
        const float2 q3 = *(const float2*)&Q3[n];
#pragma unroll
        for (int mt = 0; mt < 2; mt++) {
#pragma unroll
            for (int hh = 0; hh < 2; hh++) {
                const int rr = mt * 2 + hh;
                float z0 = fmaxf(fmaf(acc[mt][nt][hh * 2 + 0], s3.x, q3.x), 0.0f);
                float z1 = fmaxf(fmaf(acc[mt][nt][hh * 2 + 1], s3.y, q3.y), 0.0f);
                const float2 c2 = __ldg((const float2*)(h + cbase[rr] + n));
                dotp[rr] = fmaf(z0, c2.x, fmaf(z1, c2.y, dotp[rr]));
            }
        }
    }
    float* dsum = (float*)(smc + DS_OFF);
#pragma unroll
    for (int rr = 0; rr < 4; rr++) {
        float s = dotp[rr];
        s += __shfl_xor_sync(0xffffffffu, s, 1, 4);
        s += __shfl_xor_sync(0xffffffffu, s, 2, 4);
        if (tig == 0) {
            const int e = ebase + (rr >> 1) * 16 + (rr & 1) * 8 + gid;
            dsum[(wid >> 1) * TILE_E + e] = s;
        }
    }
    __syncthreads();
    if (tid < TILE_E) {
        const float* ds = (const float*)(smc + DS_OFF);
        out[e0 + tid] = (ds[tid] + ds[TILE_E + tid]) +
                        (ds[2 * TILE_E + tid] + ds[3 * TILE_E + tid]);
    }
}

// ===== launch =====
extern "C" void kernel_launch(void* const* d_in, const int* in_sizes, int n_in,
                              void* d_out, int out_size)
{
    const float* h      = (const float*)d_in[0];
    const float* g      = (const float*)d_in[1];
    const int*   eidx   = (const int*)d_in[2];
    const int*   etype  = (const int*)d_in[3];
    const float* conv_w = (const float*)d_in[4];
    const float* conv_b = (const float*)d_in[5];
    const float* fc_w   = (const float*)d_in[6];
    const float* fc_b   = (const float*)d_in[7];
    const float* bn1g   = (const float*)d_in[8];
    const float* bn1b   = (const float*)d_in[9];
    const float* bn1m   = (const float*)d_in[10];
    const float* bn1v   = (const float*)d_in[11];
    const float* bn3g   = (const float*)d_in[12];
    const float* bn3b   = (const float*)d_in[13];
    const float* bn3m   = (const float*)d_in[14];
    const float* bn3v   = (const float*)d_in[15];
    float* out = (float*)d_out;

    conve_prep<<<256, 256>>>(fc_w);

    cudaFuncSetAttribute(conve_main,
                         cudaFuncAttributeMaxDynamicSharedMemorySize, SMEM_BYTES);
    conve_main<<<E_TOT / TILE_E, NTHREADS, SMEM_BYTES>>>(
        h, g, eidx, etype, conv_w, conv_b, fc_b,
        bn1g, bn1b, bn1m, bn1v, bn3g, bn3b, bn3m, bn3v, out);
}

// round 11
// speedup vs baseline: 1.0933x; 1.0933x over previous
#include <cuda_runtime.h>
#include <cuda_fp16.h>
#include <cstdint>

#define E_TOT    131072
#define DDIM     128
#define KTOT     2048
#define TILE_E   64
#define NTHREADS 256
#define NCHUNKS  64
#define UVSTRIDE 66            // uint2 units per row (64 + 2 pad)

// ---- SMEM byte offsets ----
#define UV_OFF   0             // 64 * 66 * 8 = 33792 (u half2, v half2 interleaved)
#define S3_OFF   33792         // 128 f
#define Q3_OFF   34304
#define CA_OFF   34816         // 16 f
#define CB_OFF   34880
#define CD_OFF   34944
#define ROW_OFF  35008         // 64 i
#define COL_OFF  35264
#define TYP_OFF  35520
#define DS_OFF   35776         // 4 * 64 f = 1024
#define SMEM_BYTES 36864

// fc_w in fp16, fragment-major: [chunk][s][nblk][lane] * 4 halves (8B units)
// lane = gid*4+tig; halves = {B[c=2tig][n], B[2tig+1][n], B[8+2tig][n], B[9+2tig][n]}
// n = nblk*8+gid; j = chunk*2+s; klog = c*128+j
__device__ __half g_Bh[NCHUNKS * 2 * 16 * 32 * 4];

__device__ __forceinline__ void mma_f16(float* c, uint32_t a0, uint32_t a1,
                                        uint32_t a2, uint32_t a3,
                                        uint32_t b0, uint32_t b1) {
    asm volatile(
        "mma.sync.aligned.m16n8k16.row.col.f32.f16.f16.f32 "
        "{%0,%1,%2,%3}, {%4,%5,%6,%7}, {%8,%9}, {%0,%1,%2,%3};"
        : "+f"(c[0]), "+f"(c[1]), "+f"(c[2]), "+f"(c[3])
        : "r"(a0), "r"(a1), "r"(a2), "r"(a3), "r"(b0), "r"(b1));
}
__device__ __forceinline__ uint32_t h2u(__half2 x) { return *(uint32_t*)&x; }
__device__ __forceinline__ __half2 u2h(uint32_t x) { return *(__half2*)&x; }

// ===== prep: fragment-major fp16 B from fc_w (identical to R8/R9, proven) =====
extern "C" __global__ void conve_prep(const float* __restrict__ fc_w)
{
    const int idx = blockIdx.x * 256 + threadIdx.x;     // 0..65535 (8B units)
    const int lane  = idx & 31;
    const int nblk  = (idx >> 5) & 15;
    const int s     = (idx >> 9) & 1;
    const int chunk = idx >> 10;
    const int gid = lane >> 2;
    const int tig = lane & 3;
    const int n = nblk * 8 + gid;
    const int j = chunk * 2 + s;

    const int c0 = 2 * tig, c1 = 2 * tig + 1, c2 = 8 + 2 * tig, c3 = 9 + 2 * tig;
    float f0 = fc_w[(long)(c0 * 128 + j) * DDIM + n];
    float f1 = fc_w[(long)(c1 * 128 + j) * DDIM + n];
    float f2 = fc_w[(long)(c2 * 128 + j) * DDIM + n];
    float f3 = fc_w[(long)(c3 * 128 + j) * DDIM + n];
    __half2* dst = (__half2*)(g_Bh + (long)idx * 4);
    dst[0] = __floats2half2_rn(f0, f1);
    dst[1] = __floats2half2_rn(f2, f3);
}

// ===== main: 2 CTAs/SM, 8 uniform warps, SW-pipelined LDS, zero hot-loop sync =====
extern "C" __global__ void __launch_bounds__(NTHREADS, 2)
conve_main(const float* __restrict__ h, const float* __restrict__ g,
           const int* __restrict__ eidx, const int* __restrict__ etype,
           const float* __restrict__ conv_w, const float* __restrict__ conv_b,
           const float* __restrict__ fc_b,
           const float* __restrict__ bn1g, const float* __restrict__ bn1b,
           const float* __restrict__ bn1m, const float* __restrict__ bn1v,
           const float* __restrict__ bn3g, const float* __restrict__ bn3b,
           const float* __restrict__ bn3m, const float* __restrict__ bn3v,
           float* __restrict__ out)
{
    extern __shared__ char smc[];
    uint2* UV = (uint2*)(smc + UV_OFF);
    float* S3 = (float*)(smc + S3_OFF);
    float* Q3 = (float*)(smc + Q3_OFF);
    float* CA = (float*)(smc + CA_OFF);
    float* CB = (float*)(smc + CB_OFF);
    float* CD = (float*)(smc + CD_OFF);
    int* ROW = (int*)(smc + ROW_OFF);
    int* COL = (int*)(smc + COL_OFF);
    int* TYP = (int*)(smc + TYP_OFF);

    const int tid  = threadIdx.x;
    const int wid  = tid >> 5;
    const int lane = tid & 31;
    const int gid  = lane >> 2;
    const int tig  = lane & 3;
    const int e0   = blockIdx.x * TILE_E;

    if (tid < DDIM) {
        float s = bn3g[tid] * rsqrtf(bn3v[tid] + 1e-5f);
        S3[tid] = s;
        Q3[tid] = fc_b[tid] * s + bn3b[tid] - bn3m[tid] * s;
    }
    if (tid < TILE_E) {
        ROW[tid] = eidx[e0 + tid];
        COL[tid] = eidx[E_TOT + e0 + tid];
        TYP[tid] = etype[e0 + tid];
    }
    if (tid < 16) {
        float s1 = bn1g[0] * rsqrtf(bn1v[0] + 1e-5f);
        float b1 = bn1b[0] - bn1m[0] * s1;
        float w0 = conv_w[tid * 2], w1 = conv_w[tid * 2 + 1];
        CA[tid] = w0 * s1;
        CB[tid] = w1 * s1;
        CD[tid] = (w0 + w1) * b1 + conv_b[tid];
    }
    __syncthreads();

    // ---- gather h[row], g[type] -> interleaved fp16 SMEM UV[row][chunk], once ----
    {
        const int row = tid >> 2;
        const int jq  = tid & 3;            // 32 j-values each
        const float* hp = h + (long)ROW[row] * DDIM + jq * 32;
        const float* gp = g + (long)TYP[row] * DDIM + jq * 32;
#pragma unroll
        for (int i = 0; i < 8; i++) {
            const float4 fu = __ldg((const float4*)(hp + i * 4));
            const float4 fv = __ldg((const float4*)(gp + i * 4));
            const int ch = jq * 16 + i * 2;
            UV[row * UVSTRIDE + ch] =
                make_uint2(h2u(__floats2half2_rn(fu.x, fu.y)),
                           h2u(__floats2half2_rn(fv.x, fv.y)));
            UV[row * UVSTRIDE + ch + 1] =
                make_uint2(h2u(__floats2half2_rn(fu.z, fu.w)),
                           h2u(__floats2half2_rn(fv.z, fv.w)));
        }
    }
    __syncthreads();

    // ---- per-lane channel-pair coefficients (half2) ----
    __half2 ca2[2], cb2[2], cd2[2];
#pragma unroll
    for (int p = 0; p < 2; p++) {
        const int c = p * 8 + 2 * tig;
        ca2[p] = __floats2half2_rn(CA[c], CA[c + 1]);
        cb2[p] = __floats2half2_rn(CB[c], CB[c + 1]);
        cd2[p] = __floats2half2_rn(CD[c], CD[c + 1]);
    }
    const __half2 zero2 = __floats2half2_rn(0.0f, 0.0f);

    const int ebase = (wid & 1) * 32;
    const int nblk0 = (wid >> 1) * 4;
    const int r0    = ebase + gid;

    float acc[2][4][4];
#pragma unroll
    for (int mt = 0; mt < 2; mt++)
#pragma unroll
        for (int nt = 0; nt < 4; nt++)
#pragma unroll
            for (int q = 0; q < 4; q++) acc[mt][nt][q] = 0.0f;

    // ---- B fragments: chunk-distance ping-pong (R9 scheme, proven) ----
    const uint2* Bp = (const uint2*)g_Bh;
    uint2 vb[2][4], vbn[2][4];
#pragma unroll
    for (int s = 0; s < 2; s++)
#pragma unroll
        for (int nt = 0; nt < 4; nt++)
            vb[s][nt] = __ldg(Bp + s * 512 + (nblk0 + nt) * 32 + lane);

    // ---- u/v: prefetch chunk 0 into uv ----
    uint2 uv[4], uvn[4];
#pragma unroll
    for (int q = 0; q < 4; q++)
        uv[q] = UV[(r0 + q * 8) * UVSTRIDE];

    for (int chunk = 0; chunk < NCHUNKS; chunk++) {
        // issue next chunk's LDS immediately (consumed next iteration)
        if (chunk < NCHUNKS - 1) {
#pragma unroll
            for (int q = 0; q < 4; q++)
                uvn[q] = UV[(r0 + q * 8) * UVSTRIDE + chunk + 1];
            // prefetch next chunk's B (L2 latency hidden across the chunk)
            const uint2* bn = Bp + (chunk + 1) * 1024;
#pragma unroll
            for (int s = 0; s < 2; s++)
#pragma unroll
                for (int nt = 0; nt < 4; nt++)
                    vbn[s][nt] = __ldg(bn + s * 512 + (nblk0 + nt) * 32 + lane);
        }

#pragma unroll
        for (int s = 0; s < 2; s++) {
            uint32_t flo[4], fhi[4];
#pragma unroll
            for (int q = 0; q < 4; q++) {
                const __half2 uh = u2h(uv[q].x);
                const __half2 vh = u2h(uv[q].y);
                const __half2 uu = s ? __high2half2(uh) : __low2half2(uh);
                const __half2 vv = s ? __high2half2(vh) : __low2half2(vh);
                __half2 t0 = __hfma2(cb2[0], vv, cd2[0]);
                __half2 t1 = __hfma2(cb2[1], vv, cd2[1]);
                t0 = __hmax2(__hfma2(ca2[0], uu, t0), zero2);
                t1 = __hmax2(__hfma2(ca2[1], uu, t1), zero2);
                flo[q] = h2u(t0);
                fhi[q] = h2u(t1);
            }
#pragma unroll
            for (int nt = 0; nt < 4; nt++)
#pragma unroll
                for (int mt = 0; mt < 2; mt++)
                    mma_f16(acc[mt][nt],
                            flo[2 * mt], flo[2 * mt + 1],
                            fhi[2 * mt], fhi[2 * mt + 1],
                            vb[s][nt].x, vb[s][nt].y);
        }

#pragma unroll
        for (int q = 0; q < 4; q++) uv[q] = uvn[q];
#pragma unroll
        for (int s = 0; s < 2; s++)
#pragma unroll
            for (int nt = 0; nt < 4; nt++)
                vb[s][nt] = vbn[s][nt];
    }

    // ---- epilogue: bn3 + relu + dot(h[col]) ----
    long cbase[4];
#pragma unroll
    for (int rr = 0; rr < 4; rr++) {
        const int e = ebase + (rr >> 1) * 16 + (rr & 1) * 8 + gid;
        cbase[rr] = (long)COL[e] * DDIM;
    }
    float dotp[4] = {0.f, 0.f, 0.f, 0.f};
#pragma unroll
    for (int nt = 0; nt < 4; nt++) {
        const int n = (wid >> 1) * 32 + nt * 8 + 2 * tig;
        const float2 s3 = *(const float2*)&S3[n];
        const float2 q3 = *(const float2*)&Q3[n];
#pragma unroll
        for (int mt = 0; mt < 2; mt++) {
#pragma unroll
            for (int hh = 0; hh < 2; hh++) {
                const int rr = mt * 2 + hh;
                float z0 = fmaxf(fmaf(acc[mt][nt][hh * 2 + 0], s3.x, q3.x), 0.0f);
                float z1 = fmaxf(fmaf(acc[mt][nt][hh * 2 + 1], s3.y, q3.y), 0.0f);
                const float2 c2 = __ldg((const float2*)(h + cbase[rr] + n));
                dotp[rr] = fmaf(z0, c2.x, fmaf(z1, c2.y, dotp[rr]));
            }
        }
    }
    float* dsum = (float*)(smc + DS_OFF);
#pragma unroll
    for (int rr = 0; rr < 4; rr++) {
        float s = dotp[rr];
        s += __shfl_xor_sync(0xffffffffu, s, 1, 4);
        s += __shfl_xor_sync(0xffffffffu, s, 2, 4);
        if (tig == 0) {
            const int e = ebase + (rr >> 1) * 16 + (rr & 1) * 8 + gid;
            dsum[(wid >> 1) * TILE_E + e] = s;
        }
    }
    __syncthreads();
    if (tid < TILE_E) {
        const float* ds = (const float*)(smc + DS_OFF);
        out[e0 + tid] = (ds[tid] + ds[TILE_E + tid]) +
                        (ds[2 * TILE_E + tid] + ds[3 * TILE_E + tid]);
    }
}

// ===== launch =====
extern "C" void kernel_launch(void* const* d_in, const int* in_sizes, int n_in,
                              void* d_out, int out_size)
{
    const float* h      = (const float*)d_in[0];
    const float* g      = (const float*)d_in[1];
    const int*   eidx   = (const int*)d_in[2];
    const int*   etype  = (const int*)d_in[3];
    const float* conv_w = (const float*)d_in[4];
    const float* conv_b = (const float*)d_in[5];
    const float* fc_w   = (const float*)d_in[6];
    const float* fc_b   = (const float*)d_in[7];
    const float* bn1g   = (const float*)d_in[8];
    const float* bn1b   = (const float*)d_in[9];
    const float* bn1m   = (const float*)d_in[10];
    const float* bn1v   = (const float*)d_in[11];
    const float* bn3g   = (const float*)d_in[12];
    const float* bn3b   = (const float*)d_in[13];
    const float* bn3m   = (const float*)d_in[14];
    const float* bn3v   = (const float*)d_in[15];
    float* out = (float*)d_out;

    conve_prep<<<256, 256>>>(fc_w);

    cudaFuncSetAttribute(conve_main,
                         cudaFuncAttributeMaxDynamicSharedMemorySize, SMEM_BYTES);
    conve_main<<<E_TOT / TILE_E, NTHREADS, SMEM_BYTES>>>(
        h, g, eidx, etype, conv_w, conv_b, fc_b,
        bn1g, bn1b, bn1m, bn1v, bn3g, bn3b, bn3m, bn3v, out);
}

// round 12
// speedup vs baseline: 1.2471x; 1.1407x over previous
#include <cuda_runtime.h>
#include <cuda_fp16.h>
#include <cstdint>

#define E_TOT    131072
#define DDIM     128
#define KTOT     2048
#define TILE_E   64
#define NTHREADS 256
#define NCHUNKS  64
#define UVSTRIDE 66            // uint2 units per row (64 + 2 pad)

// ---- SMEM byte offsets ----
#define UV_OFF   0             // 64 * 66 * 8 = 33792 (u half2, v half2 interleaved)
#define S3_OFF   33792         // 128 f
#define Q3_OFF   34304
#define CA_OFF   34816         // 16 f
#define CB_OFF   34880
#define CD_OFF   34944
#define ROW_OFF  35008         // 64 i
#define COL_OFF  35264
#define TYP_OFF  35520
#define DS_OFF   35776         // 2 * 64 f = 512 B
#define SMEM_BYTES 36864

// fc_w in fp16, fragment-major: [chunk][s][nblk][lane] * 4 halves (8B units)
// lane = gid*4+tig; halves = {B[c=2tig][n], B[2tig+1][n], B[8+2tig][n], B[9+2tig][n]}
// n = nblk*8+gid; j = chunk*2+s; klog = c*128+j
__device__ __half g_Bh[NCHUNKS * 2 * 16 * 32 * 4];

__device__ __forceinline__ void mma_f16(float* c, uint32_t a0, uint32_t a1,
                                        uint32_t a2, uint32_t a3,
                                        uint32_t b0, uint32_t b1) {
    asm volatile(
        "mma.sync.aligned.m16n8k16.row.col.f32.f16.f16.f32 "
        "{%0,%1,%2,%3}, {%4,%5,%6,%7}, {%8,%9}, {%0,%1,%2,%3};"
        : "+f"(c[0]), "+f"(c[1]), "+f"(c[2]), "+f"(c[3])
        : "r"(a0), "r"(a1), "r"(a2), "r"(a3), "r"(b0), "r"(b1));
}
__device__ __forceinline__ uint32_t h2u(__half2 x) { return *(uint32_t*)&x; }
__device__ __forceinline__ __half2 u2h(uint32_t x) { return *(__half2*)&x; }

// ===== prep: fragment-major fp16 B from fc_w (identical to R8-R11, proven) =====
extern "C" __global__ void conve_prep(const float* __restrict__ fc_w)
{
    const int idx = blockIdx.x * 256 + threadIdx.x;     // 0..65535 (8B units)
    const int lane  = idx & 31;
    const int nblk  = (idx >> 5) & 15;
    const int s     = (idx >> 9) & 1;
    const int chunk = idx >> 10;
    const int gid = lane >> 2;
    const int tig = lane & 3;
    const int n = nblk * 8 + gid;
    const int j = chunk * 2 + s;

    const int c0 = 2 * tig, c1 = 2 * tig + 1, c2 = 8 + 2 * tig, c3 = 9 + 2 * tig;
    float f0 = fc_w[(long)(c0 * 128 + j) * DDIM + n];
    float f1 = fc_w[(long)(c1 * 128 + j) * DDIM + n];
    float f2 = fc_w[(long)(c2 * 128 + j) * DDIM + n];
    float f3 = fc_w[(long)(c3 * 128 + j) * DDIM + n];
    __half2* dst = (__half2*)(g_Bh + (long)idx * 4);
    dst[0] = __floats2half2_rn(f0, f1);
    dst[1] = __floats2half2_rn(f2, f3);
}

// ===== main: 2 CTAs/SM, 8 warps in 4m x 2n grid, zero hot-loop sync =====
extern "C" __global__ void __launch_bounds__(NTHREADS, 2)
conve_main(const float* __restrict__ h, const float* __restrict__ g,
           const int* __restrict__ eidx, const int* __restrict__ etype,
           const float* __restrict__ conv_w, const float* __restrict__ conv_b,
           const float* __restrict__ fc_b,
           const float* __restrict__ bn1g, const float* __restrict__ bn1b,
           const float* __restrict__ bn1m, const float* __restrict__ bn1v,
           const float* __restrict__ bn3g, const float* __restrict__ bn3b,
           const float* __restrict__ bn3m, const float* __restrict__ bn3v,
           float* __restrict__ out)
{
    extern __shared__ char smc[];
    uint2* UV = (uint2*)(smc + UV_OFF);
    float* S3 = (float*)(smc + S3_OFF);
    float* Q3 = (float*)(smc + Q3_OFF);
    float* CA = (float*)(smc + CA_OFF);
    float* CB = (float*)(smc + CB_OFF);
    float* CD = (float*)(smc + CD_OFF);
    int* ROW = (int*)(smc + ROW_OFF);
    int* COL = (int*)(smc + COL_OFF);
    int* TYP = (int*)(smc + TYP_OFF);

    const int tid  = threadIdx.x;
    const int wid  = tid >> 5;
    const int lane = tid & 31;
    const int gid  = lane >> 2;
    const int tig  = lane & 3;
    const int e0   = blockIdx.x * TILE_E;

    if (tid < DDIM) {
        float s = bn3g[tid] * rsqrtf(bn3v[tid] + 1e-5f);
        S3[tid] = s;
        Q3[tid] = fc_b[tid] * s + bn3b[tid] - bn3m[tid] * s;
    }
    if (tid < TILE_E) {
        ROW[tid] = eidx[e0 + tid];
        COL[tid] = eidx[E_TOT + e0 + tid];
        TYP[tid] = etype[e0 + tid];
    }
    if (tid < 16) {
        float s1 = bn1g[0] * rsqrtf(bn1v[0] + 1e-5f);
        float b1 = bn1b[0] - bn1m[0] * s1;
        float w0 = conv_w[tid * 2], w1 = conv_w[tid * 2 + 1];
        CA[tid] = w0 * s1;
        CB[tid] = w1 * s1;
        CD[tid] = (w0 + w1) * b1 + conv_b[tid];
    }
    __syncthreads();

    // ---- gather h[row], g[type] -> interleaved fp16 SMEM UV[row][chunk], once ----
    {
        const int row = tid >> 2;
        const int jq  = tid & 3;            // 32 j-values each
        const float* hp = h + (long)ROW[row] * DDIM + jq * 32;
        const float* gp = g + (long)TYP[row] * DDIM + jq * 32;
#pragma unroll
        for (int i = 0; i < 8; i++) {
            const float4 fu = __ldg((const float4*)(hp + i * 4));
            const float4 fv = __ldg((const float4*)(gp + i * 4));
            const int ch = jq * 16 + i * 2;
            UV[row * UVSTRIDE + ch] =
                make_uint2(h2u(__floats2half2_rn(fu.x, fu.y)),
                           h2u(__floats2half2_rn(fv.x, fv.y)));
            UV[row * UVSTRIDE + ch + 1] =
                make_uint2(h2u(__floats2half2_rn(fu.z, fu.w)),
                           h2u(__floats2half2_rn(fv.z, fv.w)));
        }
    }
    __syncthreads();

    // ---- per-lane channel-pair coefficients (half2) ----
    __half2 ca2[2], cb2[2], cd2[2];
#pragma unroll
    for (int p = 0; p < 2; p++) {
        const int c = p * 8 + 2 * tig;
        ca2[p] = __floats2half2_rn(CA[c], CA[c + 1]);
        cb2[p] = __floats2half2_rn(CB[c], CB[c + 1]);
        cd2[p] = __floats2half2_rn(CD[c], CD[c + 1]);
    }
    const __half2 zero2 = __floats2half2_rn(0.0f, 0.0f);

    // 4m x 2n warp grid: mblk = wid&3 (16 rows), nhalf = wid>>2 (64 n)
    const int ebase = (wid & 3) * 16;
    const int nhalf = wid >> 2;
    const int nblk0 = nhalf * 8;
    const int r0    = ebase + gid;

    float acc[8][4];
#pragma unroll
    for (int nt = 0; nt < 8; nt++)
#pragma unroll
        for (int q = 0; q < 4; q++) acc[nt][q] = 0.0f;

    // ---- B fragments: in-place s-step sets, refilled after use ----
    const uint2* Bp = (const uint2*)g_Bh + nblk0 * 32 + lane;
    uint2 P0[8], P1[8];
#pragma unroll
    for (int nt = 0; nt < 8; nt++) P0[nt] = __ldg(Bp + nt * 32);         // c0,s0
#pragma unroll
    for (int nt = 0; nt < 8; nt++) P1[nt] = __ldg(Bp + 512 + nt * 32);   // c0,s1

    // ---- u/v: prefetch chunk 0 ----
    uint2 uv[2], uvn[2];
#pragma unroll
    for (int q = 0; q < 2; q++)
        uv[q] = UV[(r0 + q * 8) * UVSTRIDE];

    for (int chunk = 0; chunk < NCHUNKS; chunk++) {
        const int last = (chunk == NCHUNKS - 1);
        if (!last) {
#pragma unroll
            for (int q = 0; q < 2; q++)
                uvn[q] = UV[(r0 + q * 8) * UVSTRIDE + chunk + 1];
        }

        // ---- s = 0 ----
        {
            uint32_t flo[2], fhi[2];
#pragma unroll
            for (int q = 0; q < 2; q++) {
                const __half2 uu = __low2half2(u2h(uv[q].x));
                const __half2 vv = __low2half2(u2h(uv[q].y));
                __half2 t0 = __hfma2(cb2[0], vv, cd2[0]);
                __half2 t1 = __hfma2(cb2[1], vv, cd2[1]);
                t0 = __hmax2(__hfma2(ca2[0], uu, t0), zero2);
                t1 = __hmax2(__hfma2(ca2[1], uu, t1), zero2);
                flo[q] = h2u(t0);
                fhi[q] = h2u(t1);
            }
#pragma unroll
            for (int nt = 0; nt < 8; nt++)
                mma_f16(acc[nt], flo[0], flo[1], fhi[0], fhi[1],
                        P0[nt].x, P0[nt].y);
            if (!last) {
                const uint2* bn = Bp + (chunk + 1) * 1024;
#pragma unroll
                for (int nt = 0; nt < 8; nt++) P0[nt] = __ldg(bn + nt * 32);
            }
        }
        // ---- s = 1 ----
        {
            uint32_t flo[2], fhi[2];
#pragma unroll
            for (int q = 0; q < 2; q++) {
                const __half2 uu = __high2half2(u2h(uv[q].x));
                const __half2 vv = __high2half2(u2h(uv[q].y));
                __half2 t0 = __hfma2(cb2[0], vv, cd2[0]);
                __half2 t1 = __hfma2(cb2[1], vv, cd2[1]);
                t0 = __hmax2(__hfma2(ca2[0], uu, t0), zero2);
                t1 = __hmax2(__hfma2(ca2[1], uu, t1), zero2);
                flo[q] = h2u(t0);
                fhi[q] = h2u(t1);
            }
#pragma unroll
            for (int nt = 0; nt < 8; nt++)
                mma_f16(acc[nt], flo[0], flo[1], fhi[0], fhi[1],
                        P1[nt].x, P1[nt].y);
            if (!last) {
                const uint2* bn = Bp + (chunk + 1) * 1024 + 512;
#pragma unroll
                for (int nt = 0; nt < 8; nt++) P1[nt] = __ldg(bn + nt * 32);
            }
        }
#pragma unroll
        for (int q = 0; q < 2; q++) uv[q] = uvn[q];
    }

    // ---- epilogue: bn3 + relu + dot(h[col]) over this warp's 64-col slice ----
    long cbase[2];
#pragma unroll
    for (int rr = 0; rr < 2; rr++)
        cbase[rr] = (long)COL[ebase + rr * 8 + gid] * DDIM;

    float dotp[2] = {0.f, 0.f};
#pragma unroll
    for (int nt = 0; nt < 8; nt++) {
        const int n = nhalf * 64 + nt * 8 + 2 * tig;
        const float2 s3 = *(const float2*)&S3[n];
        const float2 q3 = *(const float2*)&Q3[n];
#pragma unroll
        for (int rr = 0; rr < 2; rr++) {
            float z0 = fmaxf(fmaf(acc[nt][rr * 2 + 0], s3.x, q3.x), 0.0f);
            float z1 = fmaxf(fmaf(acc[nt][rr * 2 + 1], s3.y, q3.y), 0.0f);
            const float2 c2 = __ldg((const float2*)(h + cbase[rr] + n));
            dotp[rr] = fmaf(z0, c2.x, fmaf(z1, c2.y, dotp[rr]));
        }
    }
    float* dsum = (float*)(smc + DS_OFF);
#pragma unroll
    for (int rr = 0; rr < 2; rr++) {
        float s = dotp[rr];
        s += __shfl_xor_sync(0xffffffffu, s, 1, 4);
        s += __shfl_xor_sync(0xffffffffu, s, 2, 4);
        if (tig == 0)
            dsum[nhalf * TILE_E + ebase + rr * 8 + gid] = s;
    }
    __syncthreads();
    if (tid < TILE_E) {
        const float* ds = (const float*)(smc + DS_OFF);
        out[e0 + tid] = ds[tid] + ds[TILE_E + tid];
    }
}

// ===== launch =====
extern "C" void kernel_launch(void* const* d_in, const int* in_sizes, int n_in,
                              void* d_out, int out_size)
{
    const float* h      = (const float*)d_in[0];
    const float* g      = (const float*)d_in[1];
    const int*   eidx   = (const int*)d_in[2];
    const int*   etype  = (const int*)d_in[3];
    const float* conv_w = (const float*)d_in[4];
    const float* conv_b = (const float*)d_in[5];
    const float* fc_w   = (const float*)d_in[6];
    const float* fc_b   = (const float*)d_in[7];
    const float* bn1g   = (const float*)d_in[8];
    const float* bn1b   = (const float*)d_in[9];
    const float* bn1m   = (const float*)d_in[10];
    const float* bn1v   = (const float*)d_in[11];
    const float* bn3g   = (const float*)d_in[12];
    const float* bn3b   = (const float*)d_in[13];
    const float* bn3m   = (const float*)d_in[14];
    const float* bn3v   = (const float*)d_in[15];
    float* out = (float*)d_out;

    conve_prep<<<256, 256>>>(fc_w);

    cudaFuncSetAttribute(conve_main,
                         cudaFuncAttributeMaxDynamicSharedMemorySize, SMEM_BYTES);
    conve_main<<<E_TOT / TILE_E, NTHREADS, SMEM_BYTES>>>(
        h, g, eidx, etype, conv_w, conv_b, fc_b,
        bn1g, bn1b, bn1m, bn1v, bn3g, bn3b, bn3m, bn3v, out);
}